// round 16
// baseline (speedup 1.0000x reference)
#include <cuda_runtime.h>
#include <math.h>

// Problem constants (shapes fixed by dataset)
#define NMAX 50000
#define EMAX 800000
#define GNUM 64
// F=64, HG=HL=128; virtual feat width = 64 + 12*64 = 832

#define CSR_G 104
#define CSR_T 512

// ---------------- scratch (__device__ globals; no allocation allowed) ----------
__device__ float    d_pq[NMAX * 128];          // [p | q] per node
__device__ int      d_deg[NMAX];
__device__ int      d_off[NMAX];
__device__ int      d_fill[NMAX];
__device__ int2     d_edgeS[EMAX];             // (src, ea-bits) reordered by dst-CSR
__device__ int      d_bsum[1024];
__device__ int      d_bbase[1024];
__device__ volatile unsigned d_ctr[8];         // grid-barrier counters (self-reset)
__device__ float    d_fsum[GNUM * 832];        // per-graph summed virtual feat
__device__ float    d_z[GNUM * 128];           // z = featbar @ Wc + bc (pre-BN)
__device__ float    d_Wds[64 * 128];           // [Wd | Ws]
__device__ float    d_Wc[832 * 128];           // W_post @ W_lin
__device__ float    d_bc[128];                 // b_post @ W_lin + b_lin
__device__ float    d_v[64];                   // W_edge @ W_pre_e
__device__ float    d_cvec[64];                // b_edge @ W_pre_e + b_pre

// ------------------------- f32x2 packed helpers --------------------------------
__device__ __forceinline__ unsigned long long dup2(float x) {
    unsigned long long r;
    asm("mov.b64 %0, {%1, %1};" : "=l"(r) : "f"(x));
    return r;
}
__device__ __forceinline__ unsigned long long fma2(unsigned long long a,
                                                   unsigned long long b,
                                                   unsigned long long c) {
    unsigned long long d;
    asm("fma.rn.f32x2 %0, %1, %2, %3;" : "=l"(d) : "l"(a), "l"(b), "l"(c));
    return d;
}
__device__ __forceinline__ void unpack2(unsigned long long u, float& lo, float& hi) {
    asm("mov.b64 {%0, %1}, %2;" : "=f"(lo), "=f"(hi) : "l"(u));
}
__device__ __forceinline__ void cpasync16(unsigned dst, const void* src) {
    asm volatile("cp.async.ca.shared.global [%0], [%1], 16;" :: "r"(dst), "l"(src));
}
__device__ __forceinline__ float4 mul4(float4 a, float s) {
    return make_float4(a.x * s, a.y * s, a.z * s, a.w * s);
}

// ---------------- precomputes (weights only; fsum self-cleans) -----------------
__global__ void prep_kernel(const float* __restrict__ W_edge, const float* __restrict__ b_edge,
                            const float* __restrict__ W_pre,  const float* __restrict__ b_pre,
                            const float* __restrict__ b_post, const float* __restrict__ W_lin,
                            const float* __restrict__ b_lin) {
    int i = blockIdx.x * blockDim.x + threadIdx.x;
    if (i < 64 * 128) {
        int k = i >> 7, j = i & 127;
        d_Wds[i] = (j < 64) ? W_pre[k * 64 + j] : W_pre[(64 + k) * 64 + (j - 64)];
    } else if (i < 64 * 128 + 128) {
        int j = i - 64 * 128;
        float acc = b_lin[j];
        for (int k = 0; k < 128; k++) acc = fmaf(b_post[k], W_lin[k * 128 + j], acc);
        d_bc[j] = acc;
    } else if (i < 64 * 128 + 128 + 64) {
        int j = i - (64 * 128 + 128);
        float av = 0.f, ac = 0.f;
        for (int k = 0; k < 64; k++) {
            float w = W_pre[(128 + k) * 64 + j];
            av = fmaf(W_edge[k], w, av);
            ac = fmaf(b_edge[k], w, ac);
        }
        d_v[j]    = av;
        d_cvec[j] = ac + b_pre[j];
    }
}

// ------------- fp32x2 GEMM: BM=128, BN=128, BK=16, 256 thr, 8x8 ----------------
__global__ __launch_bounds__(256, 2) void sgemm_kernel(
    const float* __restrict__ A, const float* __restrict__ B,
    const float* __restrict__ bias, float* __restrict__ C,
    int M, int K, int lda, int ldb, int ldc) {
    __shared__ __align__(16) float As[2][128][20];
    __shared__ __align__(16) float Bs[2][16][132];

    const int tid  = threadIdx.x;
    const int row0 = blockIdx.x * 128;
    const int col0 = blockIdx.y * 128;
    const int tr   = (tid >> 4) << 3;
    const int tc   = (tid & 15) << 3;

    const unsigned sA = (unsigned)__cvta_generic_to_shared(&As[0][0][0]);
    const unsigned sB = (unsigned)__cvta_generic_to_shared(&Bs[0][0][0]);

    unsigned long long acc2[8][4];
#pragma unroll
    for (int i = 0; i < 8; i++)
#pragma unroll
        for (int p = 0; p < 4; p++) acc2[i][p] = 0ull;

    auto issue = [&](int kt, int buf) {
        int k0 = kt << 4;
#pragma unroll
        for (int t = 0; t < 2; t++) {
            int c  = tid + t * 256;
            int m  = c >> 2, kq = (c & 3) << 2;
            if (row0 + m < M)
                cpasync16(sA + (unsigned)(buf * 2560 + m * 20 + kq) * 4,
                          A + (size_t)(row0 + m) * lda + k0 + kq);
            int kr = c >> 5, n4 = (c & 31) << 2;
            cpasync16(sB + (unsigned)(buf * 2112 + kr * 132 + n4) * 4,
                      B + (size_t)(k0 + kr) * ldb + col0 + n4);
        }
        asm volatile("cp.async.commit_group;");
    };

    const int KT = K >> 4;
    issue(0, 0);

    int buf = 0;
    for (int kt = 0; kt < KT; kt++) {
        if (kt + 1 < KT) {
            issue(kt + 1, buf ^ 1);
            asm volatile("cp.async.wait_group 1;");
        } else {
            asm volatile("cp.async.wait_group 0;");
        }
        __syncthreads();

#pragma unroll
        for (int kk4 = 0; kk4 < 4; kk4++) {
            float4 a4[8];
#pragma unroll
            for (int i = 0; i < 8; i++)
                a4[i] = *reinterpret_cast<const float4*>(&As[buf][tr + i][kk4 << 2]);
#pragma unroll
            for (int kkl = 0; kkl < 4; kkl++) {
                int kk = (kk4 << 2) + kkl;
                ulonglong2 b0 = *reinterpret_cast<const ulonglong2*>(&Bs[buf][kk][tc]);
                ulonglong2 b1 = *reinterpret_cast<const ulonglong2*>(&Bs[buf][kk][tc + 4]);
                unsigned long long bv[4] = {b0.x, b0.y, b1.x, b1.y};
#pragma unroll
                for (int i = 0; i < 8; i++) {
                    float av = reinterpret_cast<const float*>(&a4[i])[kkl];
                    unsigned long long aa = dup2(av);
#pragma unroll
                    for (int p = 0; p < 4; p++) acc2[i][p] = fma2(aa, bv[p], acc2[i][p]);
                }
            }
        }
        __syncthreads();
        buf ^= 1;
    }

#pragma unroll
    for (int i = 0; i < 8; i++) {
        int gr = row0 + tr + i;
        if (gr >= M) continue;
        float cv[8];
#pragma unroll
        for (int p = 0; p < 4; p++) unpack2(acc2[i][p], cv[2 * p], cv[2 * p + 1]);
        if (bias) {
#pragma unroll
            for (int q = 0; q < 8; q++) cv[q] += bias[col0 + tc + q];
        }
        float* Cp = C + (size_t)gr * ldc + col0 + tc;
        *reinterpret_cast<float4*>(Cp)     = make_float4(cv[0], cv[1], cv[2], cv[3]);
        *reinterpret_cast<float4*>(Cp + 4) = make_float4(cv[4], cv[5], cv[6], cv[7]);
    }
}

// ---------------- fused CSR build: one kernel, grid barriers -------------------
// 104 blocks x 512 threads — co-resident on 148 SMs (deadlock-safe: the only
// concurrent kernels drain independently, freeing SMs for queued blocks).
__device__ __forceinline__ void gridbar(int idx) {
    __syncthreads();
    if (threadIdx.x == 0) {
        __threadfence();
        atomicAdd((unsigned*)&d_ctr[idx], 1u);
        while (d_ctr[idx] < (unsigned)CSR_G) { }
    }
    __syncthreads();
}

__global__ __launch_bounds__(CSR_T) void csr_kernel(const int* __restrict__ ei,
                                                    const float* __restrict__ ea,
                                                    int E, int Nn) {
    const int tid   = threadIdx.x;
    const int bid   = blockIdx.x;
    const int gsize = CSR_G * CSR_T;
    const int gid   = bid * CSR_T + tid;
    __shared__ int sh[CSR_T];

    // A: zero deg
    for (int i = gid; i < Nn; i += gsize) d_deg[i] = 0;
    gridbar(0);

    // B: count in-degrees
    for (int e = gid; e < E; e += gsize) atomicAdd(&d_deg[ei[E + e]], 1);
    gridbar(1);

    // C1: block-local sum over this block's contiguous node chunk
    const int node = bid * CSR_T + tid;
    const int v = (node < Nn) ? d_deg[node] : 0;
    sh[tid] = v;
    __syncthreads();
    for (int s = CSR_T / 2; s > 0; s >>= 1) {
        if (tid < s) sh[tid] += sh[tid + s];
        __syncthreads();
    }
    if (tid == 0) d_bsum[bid] = sh[0];
    gridbar(2);

    // C2: block 0 scans the 104 partials (128-wide Hillis-Steele)
    if (bid == 0) {
        int p = (tid < CSR_G) ? d_bsum[tid] : 0;
        sh[tid] = p;
        __syncthreads();
        for (int d = 1; d < 128; d <<= 1) {
            int u = (tid >= d && tid < 128) ? sh[tid - d] : 0;
            __syncthreads();
            if (tid < 128) sh[tid] += u;
            __syncthreads();
        }
        if (tid < CSR_G) d_bbase[tid] = sh[tid] - p;   // exclusive base
    }
    gridbar(3);

    // C3: per-block exclusive scan of chunk -> off/fill
    sh[tid] = v;
    __syncthreads();
    for (int d = 1; d < CSR_T; d <<= 1) {
        int u = (tid >= d) ? sh[tid - d] : 0;
        __syncthreads();
        sh[tid] += u;
        __syncthreads();
    }
    int excl = sh[tid] - v + d_bbase[bid];
    if (node < Nn) {
        d_off[node]  = excl;
        d_fill[node] = excl;
    }
    gridbar(4);

    // D: scatter edges into CSR order
    for (int e = gid; e < E; e += gsize) {
        int d = ei[E + e];
        int pos = atomicAdd(&d_fill[d], 1);
        d_edgeS[pos] = make_int2(ei[e], __float_as_int(ea[e]));
    }

    // finalize: last block resets all counters for the next graph replay
    __syncthreads();
    if (tid == 0) {
        __threadfence();
        unsigned old = atomicAdd((unsigned*)&d_ctr[5], 1u);
        if (old == CSR_G - 1) {
            for (int i = 0; i < 8; i++) d_ctr[i] = 0;
            __threadfence();
        }
    }
}

// ------ fused per-node aggregation + graph pooling, float4 features ------------
#define AGG_ACC(EE, QQ)                                                         \
    do {                                                                        \
        float ea_ = __int_as_float((EE).y);                                     \
        float m0 = fmaf(ea_, vf.x, t.x) + (QQ).x;                               \
        float m1 = fmaf(ea_, vf.y, t.y) + (QQ).y;                               \
        float m2 = fmaf(ea_, vf.z, t.z) + (QQ).z;                               \
        float m3 = fmaf(ea_, vf.w, t.w) + (QQ).w;                               \
        sum.x += m0; sq.x = fmaf(m0, m0, sq.x); mn.x = fminf(mn.x, m0); mx.x = fmaxf(mx.x, m0); \
        sum.y += m1; sq.y = fmaf(m1, m1, sq.y); mn.y = fminf(mn.y, m1); mx.y = fmaxf(mx.y, m1); \
        sum.z += m2; sq.z = fmaf(m2, m2, sq.z); mn.z = fminf(mn.z, m2); mx.z = fmaxf(mx.z, m2); \
        sum.w += m3; sq.w = fmaf(m3, m3, sq.w); mn.w = fminf(mn.w, m3); mx.w = fmaxf(mx.w, m3); \
    } while (0)

__global__ __launch_bounds__(256) void agg_kernel(const int* __restrict__ batch,
                                                  const float* __restrict__ x, int Nn) {
    int tid  = threadIdx.x;
    int lane = tid >> 4;          // 0..15 node lane
    int ftid = tid & 15;
    int ft   = ftid << 2;         // feature base 0,4,..,60
    int n0   = blockIdx.x * 16;
    int n    = n0 + lane;
    bool valid = n < Nn;
    bool fast  = (n0 + 15 < Nn) && (batch[n0] == batch[n0 + 15]);

    float4 vf = *reinterpret_cast<const float4*>(&d_v[ft]);
    float4 cf = *reinterpret_cast<const float4*>(&d_cvec[ft]);

    float4 mean = make_float4(0, 0, 0, 0), vmn = mean, vmx = mean, sd = mean;
    float4 xv   = mean;
    float amp = 1.f, iamp = 1.f;

    if (valid) {
        int off = d_off[n];
        int deg = d_deg[n];
        float4 pdf = *reinterpret_cast<const float4*>(&d_pq[n * 128 + ft]);
        xv = *reinterpret_cast<const float4*>(&x[n * 64 + ft]);
        float4 t = make_float4(pdf.x + cf.x, pdf.y + cf.y, pdf.z + cf.z, pdf.w + cf.w);

        float4 sum = make_float4(0, 0, 0, 0), sq = sum;
        float4 mn = make_float4(INFINITY, INFINITY, INFINITY, INFINITY);
        float4 mx = make_float4(-INFINITY, -INFINITY, -INFINITY, -INFINITY);

        int jj = 0;
        if (deg >= 4) {
            int2 pe0 = d_edgeS[off + 0], pe1 = d_edgeS[off + 1];
            int2 pe2 = d_edgeS[off + 2], pe3 = d_edgeS[off + 3];
            for (; jj + 8 <= deg; jj += 4) {
                float4 q0 = *reinterpret_cast<const float4*>(&d_pq[pe0.x * 128 + 64 + ft]);
                float4 q1 = *reinterpret_cast<const float4*>(&d_pq[pe1.x * 128 + 64 + ft]);
                float4 q2 = *reinterpret_cast<const float4*>(&d_pq[pe2.x * 128 + 64 + ft]);
                float4 q3 = *reinterpret_cast<const float4*>(&d_pq[pe3.x * 128 + 64 + ft]);
                int2 ne0 = d_edgeS[off + jj + 4], ne1 = d_edgeS[off + jj + 5];
                int2 ne2 = d_edgeS[off + jj + 6], ne3 = d_edgeS[off + jj + 7];
                AGG_ACC(pe0, q0); AGG_ACC(pe1, q1); AGG_ACC(pe2, q2); AGG_ACC(pe3, q3);
                pe0 = ne0; pe1 = ne1; pe2 = ne2; pe3 = ne3;
            }
            {   // pending full group
                float4 q0 = *reinterpret_cast<const float4*>(&d_pq[pe0.x * 128 + 64 + ft]);
                float4 q1 = *reinterpret_cast<const float4*>(&d_pq[pe1.x * 128 + 64 + ft]);
                float4 q2 = *reinterpret_cast<const float4*>(&d_pq[pe2.x * 128 + 64 + ft]);
                float4 q3 = *reinterpret_cast<const float4*>(&d_pq[pe3.x * 128 + 64 + ft]);
                AGG_ACC(pe0, q0); AGG_ACC(pe1, q1); AGG_ACC(pe2, q2); AGG_ACC(pe3, q3);
                jj += 4;
            }
        }
        for (; jj < deg; jj++) {
            int2 ee = d_edgeS[off + jj];
            float4 qq = *reinterpret_cast<const float4*>(&d_pq[ee.x * 128 + 64 + ft]);
            AGG_ACC(ee, qq);
        }

        float cnt1 = fmaxf((float)deg, 1.f);
        float inv  = 1.f / cnt1;
        mean = mul4(sum, inv);
        float4 mean2 = mul4(sq, inv);
        sd.x = sqrtf(fmaxf(mean2.x - mean.x * mean.x, 0.f) + 1e-5f);
        sd.y = sqrtf(fmaxf(mean2.y - mean.y * mean.y, 0.f) + 1e-5f);
        sd.z = sqrtf(fmaxf(mean2.z - mean.z * mean.z, 0.f) + 1e-5f);
        sd.w = sqrtf(fmaxf(mean2.w - mean.w * mean.w, 0.f) + 1e-5f);
        bool has = deg > 0;
        vmn = has ? mn : make_float4(0, 0, 0, 0);
        vmx = has ? mx : make_float4(0, 0, 0, 0);
        amp  = logf(cnt1 + 1.f) * (1.0f / 2.19722457733621938f);   // / log(9)
        iamp = 1.f / amp;
    }

    if (fast) {
        __shared__ float S[16 * 64];   // [lane][feature]
        float* F = d_fsum + batch[n0] * 832;
#pragma unroll
        for (int c = 0; c < 13; c++) {
            float4 cv;
            if      (c == 0)  cv = xv;
            else if (c == 1)  cv = mean;
            else if (c == 2)  cv = vmn;
            else if (c == 3)  cv = vmx;
            else if (c == 4)  cv = sd;
            else if (c == 5)  cv = mul4(mean, amp);
            else if (c == 6)  cv = mul4(vmn, amp);
            else if (c == 7)  cv = mul4(vmx, amp);
            else if (c == 8)  cv = mul4(sd, amp);
            else if (c == 9)  cv = mul4(mean, iamp);
            else if (c == 10) cv = mul4(vmn, iamp);
            else if (c == 11) cv = mul4(vmx, iamp);
            else              cv = mul4(sd, iamp);
            *reinterpret_cast<float4*>(&S[lane * 64 + ft]) = cv;
            __syncthreads();
            if (tid < 64) {
                float s = 0.f;
#pragma unroll
                for (int l = 0; l < 16; l++) s += S[l * 64 + tid];
                atomicAdd(&F[c * 64 + tid], s);
            }
            __syncthreads();
        }
    } else if (valid) {
        float* F = d_fsum + batch[n] * 832;
        float4 ch[13];
        ch[0] = xv;  ch[1] = mean; ch[2] = vmn; ch[3] = vmx; ch[4] = sd;
        ch[5] = mul4(mean, amp);  ch[6]  = mul4(vmn, amp);  ch[7]  = mul4(vmx, amp);  ch[8]  = mul4(sd, amp);
        ch[9] = mul4(mean, iamp); ch[10] = mul4(vmn, iamp); ch[11] = mul4(vmx, iamp); ch[12] = mul4(sd, iamp);
#pragma unroll
        for (int c = 0; c < 13; c++) {
            atomicAdd(&F[c * 64 + ft + 0], ch[c].x);
            atomicAdd(&F[c * 64 + ft + 1], ch[c].y);
            atomicAdd(&F[c * 64 + ft + 2], ch[c].z);
            atomicAdd(&F[c * 64 + ft + 3], ch[c].w);
        }
    }
}

// ------------- z = (fsum/cnt) @ Wc + bc; self-cleans fsum ----------------------
__global__ __launch_bounds__(512) void zsmall_kernel(const int* __restrict__ batch, int Nn) {
    __shared__ float Fs[832];
    __shared__ float red[512];
    int g = blockIdx.x;
    int tid = threadIdx.x;
    int j = tid & 127, piece = tid >> 7;

    int lo = 0, hi = Nn;
    while (lo < hi) { int m = (lo + hi) >> 1; if (batch[m] < g) lo = m + 1; else hi = m; }
    int lo2 = lo, hi2 = Nn;
    while (lo2 < hi2) { int m = (lo2 + hi2) >> 1; if (batch[m] < g + 1) lo2 = m + 1; else hi2 = m; }
    float inv = 1.f / fmaxf((float)(lo2 - lo), 1.f);

    for (int i = tid; i < 832; i += 512) {
        Fs[i] = d_fsum[g * 832 + i] * inv;
        d_fsum[g * 832 + i] = 0.f;        // restore zero for next replay
    }
    __syncthreads();

    int k0 = piece * 208;
    float a0 = (piece == 0) ? d_bc[j] : 0.f, a1 = 0.f, a2 = 0.f, a3 = 0.f;
#pragma unroll 4
    for (int k = 0; k < 208; k += 4) {
        a0 = fmaf(Fs[k0 + k],     d_Wc[(k0 + k)     * 128 + j], a0);
        a1 = fmaf(Fs[k0 + k + 1], d_Wc[(k0 + k + 1) * 128 + j], a1);
        a2 = fmaf(Fs[k0 + k + 2], d_Wc[(k0 + k + 2) * 128 + j], a2);
        a3 = fmaf(Fs[k0 + k + 3], d_Wc[(k0 + k + 3) * 128 + j], a3);
    }
    red[tid] = (a0 + a1) + (a2 + a3);
    __syncthreads();
    if (piece == 0)
        d_z[g * 128 + j] = (red[j] + red[128 + j]) + (red[256 + j] + red[384 + j]);
}

// ------------------------------- MLP head --------------------------------------
__device__ __forceinline__ void mlp_stats(float ps, float pq2, int rr, int j,
                                          float* redS, float* redQ,
                                          float* sgS, float* sbS,
                                          const float* __restrict__ g,
                                          const float* __restrict__ be) {
    redS[rr * 128 + j] = ps;
    redQ[rr * 128 + j] = pq2;
    __syncthreads();
    if (rr == 0) {
        float s = 0.f, q = 0.f;
#pragma unroll
        for (int r = 0; r < 8; r++) { s += redS[r * 128 + j]; q += redQ[r * 128 + j]; }
        float mu  = s * (1.f / 64.f);
        float var = q * (1.f / 64.f) - mu * mu;
        float is  = rsqrtf(fmaxf(var, 0.f) + 1e-5f);
        float sg  = g[j] * is;
        sgS[j] = sg;
        sbS[j] = be[j] - mu * sg;
    }
    __syncthreads();
}

__device__ __forceinline__ void mlp_layer(float* S, float* redS, float* redQ,
                                          float* sgS, float* sbS,
                                          const float* __restrict__ W, const float* __restrict__ b,
                                          const float* __restrict__ g, const float* __restrict__ be,
                                          int rr, int j, float* rsave, const float* radd) {
    const int i0 = rr * 8;
    unsigned long long acc2[4];
    unsigned long long binit = dup2(b[j]);
#pragma unroll
    for (int p = 0; p < 4; p++) acc2[p] = binit;

    for (int k = 0; k < 128; k++) {
        unsigned long long w2 = dup2(W[k * 128 + j]);
        const unsigned long long* Z =
            reinterpret_cast<const unsigned long long*>(&S[k * 66 + i0]);
#pragma unroll
        for (int p = 0; p < 4; p++) acc2[p] = fma2(Z[p], w2, acc2[p]);
    }

    float acc[8];
#pragma unroll
    for (int p = 0; p < 4; p++) unpack2(acc2[p], acc[2 * p], acc[2 * p + 1]);

    float ps = 0.f, pq2 = 0.f;
#pragma unroll
    for (int u = 0; u < 8; u++) { ps += acc[u]; pq2 = fmaf(acc[u], acc[u], pq2); }
    mlp_stats(ps, pq2, rr, j, redS, redQ, sgS, sbS, g, be);   // syncs cover S reads

    float sg = sgS[j], sb = sbS[j];
#pragma unroll
    for (int p = 0; p < 4; p++) {
        float v0 = acc[2 * p] * sg + sb;
        float v1 = acc[2 * p + 1] * sg + sb;
        if (radd) { v0 += radd[2 * p]; v1 += radd[2 * p + 1]; }
        v0 = fmaxf(v0, 0.f);
        v1 = fmaxf(v1, 0.f);
        *reinterpret_cast<float2*>(&S[j * 66 + i0 + 2 * p]) = make_float2(v0, v1);
        if (rsave) { rsave[2 * p] = v0; rsave[2 * p + 1] = v1; }
    }
    __syncthreads();
}

__global__ __launch_bounds__(1024) void mlp_kernel(
        const float* __restrict__ g1,  const float* __restrict__ be1,
        const float* __restrict__ W2,  const float* __restrict__ b2,
        const float* __restrict__ g2,  const float* __restrict__ be2,
        const float* __restrict__ Wr1, const float* __restrict__ br1,
        const float* __restrict__ gr1, const float* __restrict__ ber1,
        const float* __restrict__ Wr2, const float* __restrict__ br2,
        const float* __restrict__ gr2, const float* __restrict__ ber2,
        const float* __restrict__ Wout, const float* __restrict__ bout,
        float* __restrict__ out) {
    __shared__ float S[128 * 66];        // transposed activations, padded
    __shared__ float redS[8 * 128];
    __shared__ float redQ[8 * 128];
    __shared__ float sgS[128], sbS[128];
    int tid = threadIdx.x;
    int rr = tid >> 7, j = tid & 127;
    const int i0 = rr * 8;

    float v8[8];
#pragma unroll
    for (int u = 0; u < 8; u++) v8[u] = d_z[(i0 + u) * 128 + j];
    {
        float ps = 0.f, pq2 = 0.f;
#pragma unroll
        for (int u = 0; u < 8; u++) { ps += v8[u]; pq2 = fmaf(v8[u], v8[u], pq2); }
        mlp_stats(ps, pq2, rr, j, redS, redQ, sgS, sbS, g1, be1);
        float sg = sgS[j], sb = sbS[j];
#pragma unroll
        for (int p = 0; p < 4; p++) {
            float v0 = fmaxf(v8[2 * p] * sg + sb, 0.f);
            float v1 = fmaxf(v8[2 * p + 1] * sg + sb, 0.f);
            *reinterpret_cast<float2*>(&S[j * 66 + i0 + 2 * p]) = make_float2(v0, v1);
        }
        __syncthreads();
    }

    float res[8];
    mlp_layer(S, redS, redQ, sgS, sbS, W2,  b2,  g2,  be2,  rr, j, res,    nullptr);
    mlp_layer(S, redS, redQ, sgS, sbS, Wr1, br1, gr1, ber1, rr, j, nullptr, nullptr);
    mlp_layer(S, redS, redQ, sgS, sbS, Wr2, br2, gr2, ber2, rr, j, nullptr, res);

    if (tid < 64) {
        float a = bout[0];
        for (int k = 0; k < 128; k++) a = fmaf(S[k * 66 + tid], Wout[k], a);
        out[tid] = a;
    }
}

// --------------------------------- launch --------------------------------------
extern "C" void kernel_launch(void* const* d_in, const int* in_sizes, int n_in,
                              void* d_out, int out_size) {
    const float* x      = (const float*)d_in[0];
    const int*   ei     = (const int*)d_in[1];
    const float* ea     = (const float*)d_in[2];
    const int*   batch  = (const int*)d_in[3];
    const float* W_edge = (const float*)d_in[4];
    const float* b_edge = (const float*)d_in[5];
    const float* W_pre  = (const float*)d_in[6];
    const float* b_pre  = (const float*)d_in[7];
    const float* W_post = (const float*)d_in[8];
    const float* b_post = (const float*)d_in[9];
    const float* W_lin  = (const float*)d_in[10];
    const float* b_lin  = (const float*)d_in[11];
    const float* g1  = (const float*)d_in[12];
    const float* be1 = (const float*)d_in[13];
    const float* W2  = (const float*)d_in[14];
    const float* b2  = (const float*)d_in[15];
    const float* g2  = (const float*)d_in[16];
    const float* be2 = (const float*)d_in[17];
    const float* Wr1 = (const float*)d_in[18];
    const float* br1 = (const float*)d_in[19];
    const float* gr1 = (const float*)d_in[20];
    const float* ber1= (const float*)d_in[21];
    const float* Wr2 = (const float*)d_in[22];
    const float* br2 = (const float*)d_in[23];
    const float* gr2 = (const float*)d_in[24];
    const float* ber2= (const float*)d_in[25];
    const float* Wout= (const float*)d_in[26];
    const float* bout= (const float*)d_in[27];
    float* out = (float*)d_out;

    const int Nn = in_sizes[0] / 64;
    const int E  = in_sizes[2];

    void *p_pq, *p_Wds, *p_Wc;
    cudaGetSymbolAddress(&p_pq,  d_pq);
    cudaGetSymbolAddress(&p_Wds, d_Wds);
    cudaGetSymbolAddress(&p_Wc,  d_Wc);

    // one-time stream/event resources (resource caching only; captured work is
    // identical on every call — record/wait are re-issued each launch)
    static cudaStream_t s_csr = nullptr;
    static cudaEvent_t  ev_fork = nullptr, ev_join = nullptr, ev_wc = nullptr;
    if (!s_csr) {
        cudaStreamCreateWithFlags(&s_csr, cudaStreamNonBlocking);
        cudaEventCreateWithFlags(&ev_fork, cudaEventDisableTiming);
        cudaEventCreateWithFlags(&ev_join, cudaEventDisableTiming);
        cudaEventCreateWithFlags(&ev_wc,   cudaEventDisableTiming);
    }

    // fork: fused CSR (+Wc) on s_csr, prep/pq on the launch stream
    cudaEventRecord(ev_fork, 0);
    cudaStreamWaitEvent(s_csr, ev_fork, 0);

    csr_kernel<<<CSR_G, CSR_T, 0, s_csr>>>(ei, ea, E, Nn);
    cudaEventRecord(ev_join, s_csr);
    // Wc = W_post @ W_lin (only needed by zsmall) — overlaps agg on main stream
    {
        dim3 g((832 + 127) / 128, 1);
        sgemm_kernel<<<g, 256, 0, s_csr>>>(W_post, W_lin, nullptr, (float*)p_Wc,
                                           832, 128, 128, 128, 128);
    }
    cudaEventRecord(ev_wc, s_csr);

    prep_kernel<<<(64 * 128 + 128 + 64 + 255) / 256, 256>>>(W_edge, b_edge, W_pre, b_pre,
                                                            b_post, W_lin, b_lin);
    // pq = x @ [Wd|Ws]      [N,64] @ [64,128]
    {
        dim3 g((Nn + 127) / 128, 1);
        sgemm_kernel<<<g, 256>>>(x, (const float*)p_Wds, nullptr, (float*)p_pq,
                                 Nn, 64, 64, 128, 128);
    }

    // join: aggregation needs CSR + pq + v/cvec(prep)
    cudaStreamWaitEvent(0, ev_join, 0);
    agg_kernel<<<(Nn + 15) / 16, 256>>>(batch, x, Nn);
    cudaStreamWaitEvent(0, ev_wc, 0);
    zsmall_kernel<<<GNUM, 512>>>(batch, Nn);
    mlp_kernel<<<1, 1024>>>(g1, be1, W2, b2, g2, be2, Wr1, br1, gr1, ber1,
                            Wr2, br2, gr2, ber2, Wout, bout, out);
}

// round 17
// speedup vs baseline: 1.0009x; 1.0009x over previous
#include <cuda_runtime.h>
#include <math.h>

// Problem constants (shapes fixed by dataset)
#define NMAX 50000
#define EMAX 800000
#define GNUM 64
// F=64, HG=HL=128; virtual feat width = 64 + 12*64 = 832

#define SCAN_G 104
#define SCAN_T 512

// ---------------- scratch (__device__ globals; no allocation allowed) ----------
__device__ float    d_pq[NMAX * 128];          // [p | q] per node
__device__ int      d_deg[NMAX];
__device__ int      d_off[NMAX];
__device__ int      d_rank[EMAX];              // within-dst rank of each edge
__device__ int2     d_edgeS[EMAX];             // (src, ea-bits) reordered by dst-CSR
__device__ int      d_bsum[1024];
__device__ int      d_bbase[1024];
__device__ volatile unsigned d_ctr[4];         // grid-barrier counters (self-reset)
__device__ float    d_fsum[GNUM * 832];        // per-graph summed virtual feat
__device__ float    d_z[GNUM * 128];           // z = featbar @ Wc + bc (pre-BN)
__device__ float    d_Wds[64 * 128];           // [Wd | Ws]
__device__ float    d_Wc[832 * 128];           // W_post @ W_lin
__device__ float    d_bc[128];                 // b_post @ W_lin + b_lin
__device__ float    d_v[64];                   // W_edge @ W_pre_e
__device__ float    d_cvec[64];                // b_edge @ W_pre_e + b_pre

// ------------------------- f32x2 packed helpers --------------------------------
__device__ __forceinline__ unsigned long long dup2(float x) {
    unsigned long long r;
    asm("mov.b64 %0, {%1, %1};" : "=l"(r) : "f"(x));
    return r;
}
__device__ __forceinline__ unsigned long long fma2(unsigned long long a,
                                                   unsigned long long b,
                                                   unsigned long long c) {
    unsigned long long d;
    asm("fma.rn.f32x2 %0, %1, %2, %3;" : "=l"(d) : "l"(a), "l"(b), "l"(c));
    return d;
}
__device__ __forceinline__ void unpack2(unsigned long long u, float& lo, float& hi) {
    asm("mov.b64 {%0, %1}, %2;" : "=f"(lo), "=f"(hi) : "l"(u));
}
__device__ __forceinline__ void cpasync16(unsigned dst, const void* src) {
    asm volatile("cp.async.ca.shared.global [%0], [%1], 16;" :: "r"(dst), "l"(src));
}
__device__ __forceinline__ float4 mul4(float4 a, float s) {
    return make_float4(a.x * s, a.y * s, a.z * s, a.w * s);
}

// --------------------- deg zero (s_csr stream, before count) -------------------
__global__ void initdeg_kernel(int Nn) {
    int i = blockIdx.x * blockDim.x + threadIdx.x;
    if (i < Nn) d_deg[i] = 0;
}

// ---------------- precomputes (weights only; fsum self-cleans) -----------------
__global__ void prep_kernel(const float* __restrict__ W_edge, const float* __restrict__ b_edge,
                            const float* __restrict__ W_pre,  const float* __restrict__ b_pre,
                            const float* __restrict__ b_post, const float* __restrict__ W_lin,
                            const float* __restrict__ b_lin) {
    int i = blockIdx.x * blockDim.x + threadIdx.x;
    if (i < 64 * 128) {
        int k = i >> 7, j = i & 127;
        d_Wds[i] = (j < 64) ? W_pre[k * 64 + j] : W_pre[(64 + k) * 64 + (j - 64)];
    } else if (i < 64 * 128 + 128) {
        int j = i - 64 * 128;
        float acc = b_lin[j];
        for (int k = 0; k < 128; k++) acc = fmaf(b_post[k], W_lin[k * 128 + j], acc);
        d_bc[j] = acc;
    } else if (i < 64 * 128 + 128 + 64) {
        int j = i - (64 * 128 + 128);
        float av = 0.f, ac = 0.f;
        for (int k = 0; k < 64; k++) {
            float w = W_pre[(128 + k) * 64 + j];
            av = fmaf(W_edge[k], w, av);
            ac = fmaf(b_edge[k], w, ac);
        }
        d_v[j]    = av;
        d_cvec[j] = ac + b_pre[j];
    }
}

// ------------- fp32x2 GEMM: BM=128, BN=128, BK=16, 256 thr, 8x8 ----------------
__global__ __launch_bounds__(256, 2) void sgemm_kernel(
    const float* __restrict__ A, const float* __restrict__ B,
    const float* __restrict__ bias, float* __restrict__ C,
    int M, int K, int lda, int ldb, int ldc) {
    __shared__ __align__(16) float As[2][128][20];
    __shared__ __align__(16) float Bs[2][16][132];

    const int tid  = threadIdx.x;
    const int row0 = blockIdx.x * 128;
    const int col0 = blockIdx.y * 128;
    const int tr   = (tid >> 4) << 3;
    const int tc   = (tid & 15) << 3;

    const unsigned sA = (unsigned)__cvta_generic_to_shared(&As[0][0][0]);
    const unsigned sB = (unsigned)__cvta_generic_to_shared(&Bs[0][0][0]);

    unsigned long long acc2[8][4];
#pragma unroll
    for (int i = 0; i < 8; i++)
#pragma unroll
        for (int p = 0; p < 4; p++) acc2[i][p] = 0ull;

    auto issue = [&](int kt, int buf) {
        int k0 = kt << 4;
#pragma unroll
        for (int t = 0; t < 2; t++) {
            int c  = tid + t * 256;
            int m  = c >> 2, kq = (c & 3) << 2;
            if (row0 + m < M)
                cpasync16(sA + (unsigned)(buf * 2560 + m * 20 + kq) * 4,
                          A + (size_t)(row0 + m) * lda + k0 + kq);
            int kr = c >> 5, n4 = (c & 31) << 2;
            cpasync16(sB + (unsigned)(buf * 2112 + kr * 132 + n4) * 4,
                      B + (size_t)(k0 + kr) * ldb + col0 + n4);
        }
        asm volatile("cp.async.commit_group;");
    };

    const int KT = K >> 4;
    issue(0, 0);

    int buf = 0;
    for (int kt = 0; kt < KT; kt++) {
        if (kt + 1 < KT) {
            issue(kt + 1, buf ^ 1);
            asm volatile("cp.async.wait_group 1;");
        } else {
            asm volatile("cp.async.wait_group 0;");
        }
        __syncthreads();

#pragma unroll
        for (int kk4 = 0; kk4 < 4; kk4++) {
            float4 a4[8];
#pragma unroll
            for (int i = 0; i < 8; i++)
                a4[i] = *reinterpret_cast<const float4*>(&As[buf][tr + i][kk4 << 2]);
#pragma unroll
            for (int kkl = 0; kkl < 4; kkl++) {
                int kk = (kk4 << 2) + kkl;
                ulonglong2 b0 = *reinterpret_cast<const ulonglong2*>(&Bs[buf][kk][tc]);
                ulonglong2 b1 = *reinterpret_cast<const ulonglong2*>(&Bs[buf][kk][tc + 4]);
                unsigned long long bv[4] = {b0.x, b0.y, b1.x, b1.y};
#pragma unroll
                for (int i = 0; i < 8; i++) {
                    float av = reinterpret_cast<const float*>(&a4[i])[kkl];
                    unsigned long long aa = dup2(av);
#pragma unroll
                    for (int p = 0; p < 4; p++) acc2[i][p] = fma2(aa, bv[p], acc2[i][p]);
                }
            }
        }
        __syncthreads();
        buf ^= 1;
    }

#pragma unroll
    for (int i = 0; i < 8; i++) {
        int gr = row0 + tr + i;
        if (gr >= M) continue;
        float cv[8];
#pragma unroll
        for (int p = 0; p < 4; p++) unpack2(acc2[i][p], cv[2 * p], cv[2 * p + 1]);
        if (bias) {
#pragma unroll
            for (int q = 0; q < 8; q++) cv[q] += bias[col0 + tc + q];
        }
        float* Cp = C + (size_t)gr * ldc + col0 + tc;
        *reinterpret_cast<float4*>(Cp)     = make_float4(cv[0], cv[1], cv[2], cv[3]);
        *reinterpret_cast<float4*>(Cp + 4) = make_float4(cv[4], cv[5], cv[6], cv[7]);
    }
}

// ------------------------------- CSR build -------------------------------------
// count also records each edge's within-dst rank -> scatter needs no atomics.
__global__ void count_kernel(const int* __restrict__ ei, int E) {
    int e = blockIdx.x * blockDim.x + threadIdx.x;
    if (e >= E) return;
    d_rank[e] = atomicAdd(&d_deg[ei[E + e]], 1);
}

// fused 3-phase scan: 104 blocks x 512 threads, 2 grid barriers (tiny work).
__device__ __forceinline__ void gridbar(int idx) {
    __syncthreads();
    if (threadIdx.x == 0) {
        __threadfence();
        atomicAdd((unsigned*)&d_ctr[idx], 1u);
        while (d_ctr[idx] < (unsigned)SCAN_G) { }
    }
    __syncthreads();
}

__global__ __launch_bounds__(SCAN_T) void scan_kernel(int Nn) {
    const int tid = threadIdx.x;
    const int bid = blockIdx.x;
    const int node = bid * SCAN_T + tid;
    __shared__ int sh[SCAN_T];

    // P1: block-local sum of this block's contiguous node chunk
    const int v = (node < Nn) ? d_deg[node] : 0;
    sh[tid] = v;
    __syncthreads();
    for (int s = SCAN_T / 2; s > 0; s >>= 1) {
        if (tid < s) sh[tid] += sh[tid + s];
        __syncthreads();
    }
    if (tid == 0) d_bsum[bid] = sh[0];
    gridbar(0);

    // P2: block 0 scans the 104 partials (128-wide Hillis-Steele)
    if (bid == 0) {
        int p = (tid < SCAN_G) ? d_bsum[tid] : 0;
        sh[tid] = p;
        __syncthreads();
        for (int d = 1; d < 128; d <<= 1) {
            int u = (tid >= d && tid < 128) ? sh[tid - d] : 0;
            __syncthreads();
            if (tid < 128) sh[tid] += u;
            __syncthreads();
        }
        if (tid < SCAN_G) d_bbase[tid] = sh[tid] - p;   // exclusive base
    }
    gridbar(1);

    // P3: per-block exclusive scan of chunk -> d_off
    sh[tid] = v;
    __syncthreads();
    for (int d = 1; d < SCAN_T; d <<= 1) {
        int u = (tid >= d) ? sh[tid - d] : 0;
        __syncthreads();
        sh[tid] += u;
        __syncthreads();
    }
    if (node < Nn) d_off[node] = sh[tid] - v + d_bbase[bid];

    // reset counters for next replay (last block to finish)
    __syncthreads();
    if (tid == 0) {
        __threadfence();
        unsigned old = atomicAdd((unsigned*)&d_ctr[2], 1u);
        if (old == SCAN_G - 1) {
            d_ctr[0] = 0; d_ctr[1] = 0; d_ctr[2] = 0;
            __threadfence();
        }
    }
}

// atomic-free scatter: slot = off[dst] + rank[e]
__global__ void scatter_kernel(const int* __restrict__ ei, const float* __restrict__ ea, int E) {
    int e = blockIdx.x * blockDim.x + threadIdx.x;
    if (e >= E) return;
    int d = ei[E + e];
    int pos = d_off[d] + d_rank[e];
    d_edgeS[pos] = make_int2(ei[e], __float_as_int(ea[e]));
}

// ------ fused per-node aggregation + graph pooling, float4 features ------------
#define AGG_ACC(EE, QQ)                                                         \
    do {                                                                        \
        float ea_ = __int_as_float((EE).y);                                     \
        float m0 = fmaf(ea_, vf.x, t.x) + (QQ).x;                               \
        float m1 = fmaf(ea_, vf.y, t.y) + (QQ).y;                               \
        float m2 = fmaf(ea_, vf.z, t.z) + (QQ).z;                               \
        float m3 = fmaf(ea_, vf.w, t.w) + (QQ).w;                               \
        sum.x += m0; sq.x = fmaf(m0, m0, sq.x); mn.x = fminf(mn.x, m0); mx.x = fmaxf(mx.x, m0); \
        sum.y += m1; sq.y = fmaf(m1, m1, sq.y); mn.y = fminf(mn.y, m1); mx.y = fmaxf(mx.y, m1); \
        sum.z += m2; sq.z = fmaf(m2, m2, sq.z); mn.z = fminf(mn.z, m2); mx.z = fmaxf(mx.z, m2); \
        sum.w += m3; sq.w = fmaf(m3, m3, sq.w); mn.w = fminf(mn.w, m3); mx.w = fmaxf(mx.w, m3); \
    } while (0)

__global__ __launch_bounds__(256) void agg_kernel(const int* __restrict__ batch,
                                                  const float* __restrict__ x, int Nn) {
    int tid  = threadIdx.x;
    int lane = tid >> 4;          // 0..15 node lane
    int ftid = tid & 15;
    int ft   = ftid << 2;         // feature base 0,4,..,60
    int n0   = blockIdx.x * 16;
    int n    = n0 + lane;
    bool valid = n < Nn;
    bool fast  = (n0 + 15 < Nn) && (batch[n0] == batch[n0 + 15]);

    float4 vf = *reinterpret_cast<const float4*>(&d_v[ft]);
    float4 cf = *reinterpret_cast<const float4*>(&d_cvec[ft]);

    float4 mean = make_float4(0, 0, 0, 0), vmn = mean, vmx = mean, sd = mean;
    float4 xv   = mean;
    float amp = 1.f, iamp = 1.f;

    if (valid) {
        int off = d_off[n];
        int deg = d_deg[n];
        float4 pdf = *reinterpret_cast<const float4*>(&d_pq[n * 128 + ft]);
        xv = *reinterpret_cast<const float4*>(&x[n * 64 + ft]);
        float4 t = make_float4(pdf.x + cf.x, pdf.y + cf.y, pdf.z + cf.z, pdf.w + cf.w);

        float4 sum = make_float4(0, 0, 0, 0), sq = sum;
        float4 mn = make_float4(INFINITY, INFINITY, INFINITY, INFINITY);
        float4 mx = make_float4(-INFINITY, -INFINITY, -INFINITY, -INFINITY);

        int jj = 0;
        if (deg >= 4) {
            int2 pe0 = d_edgeS[off + 0], pe1 = d_edgeS[off + 1];
            int2 pe2 = d_edgeS[off + 2], pe3 = d_edgeS[off + 3];
            for (; jj + 8 <= deg; jj += 4) {
                float4 q0 = *reinterpret_cast<const float4*>(&d_pq[pe0.x * 128 + 64 + ft]);
                float4 q1 = *reinterpret_cast<const float4*>(&d_pq[pe1.x * 128 + 64 + ft]);
                float4 q2 = *reinterpret_cast<const float4*>(&d_pq[pe2.x * 128 + 64 + ft]);
                float4 q3 = *reinterpret_cast<const float4*>(&d_pq[pe3.x * 128 + 64 + ft]);
                int2 ne0 = d_edgeS[off + jj + 4], ne1 = d_edgeS[off + jj + 5];
                int2 ne2 = d_edgeS[off + jj + 6], ne3 = d_edgeS[off + jj + 7];
                AGG_ACC(pe0, q0); AGG_ACC(pe1, q1); AGG_ACC(pe2, q2); AGG_ACC(pe3, q3);
                pe0 = ne0; pe1 = ne1; pe2 = ne2; pe3 = ne3;
            }
            {   // pending full group
                float4 q0 = *reinterpret_cast<const float4*>(&d_pq[pe0.x * 128 + 64 + ft]);
                float4 q1 = *reinterpret_cast<const float4*>(&d_pq[pe1.x * 128 + 64 + ft]);
                float4 q2 = *reinterpret_cast<const float4*>(&d_pq[pe2.x * 128 + 64 + ft]);
                float4 q3 = *reinterpret_cast<const float4*>(&d_pq[pe3.x * 128 + 64 + ft]);
                AGG_ACC(pe0, q0); AGG_ACC(pe1, q1); AGG_ACC(pe2, q2); AGG_ACC(pe3, q3);
                jj += 4;
            }
        }
        for (; jj < deg; jj++) {
            int2 ee = d_edgeS[off + jj];
            float4 qq = *reinterpret_cast<const float4*>(&d_pq[ee.x * 128 + 64 + ft]);
            AGG_ACC(ee, qq);
        }

        float cnt1 = fmaxf((float)deg, 1.f);
        float inv  = 1.f / cnt1;
        mean = mul4(sum, inv);
        float4 mean2 = mul4(sq, inv);
        sd.x = sqrtf(fmaxf(mean2.x - mean.x * mean.x, 0.f) + 1e-5f);
        sd.y = sqrtf(fmaxf(mean2.y - mean.y * mean.y, 0.f) + 1e-5f);
        sd.z = sqrtf(fmaxf(mean2.z - mean.z * mean.z, 0.f) + 1e-5f);
        sd.w = sqrtf(fmaxf(mean2.w - mean.w * mean.w, 0.f) + 1e-5f);
        bool has = deg > 0;
        vmn = has ? mn : make_float4(0, 0, 0, 0);
        vmx = has ? mx : make_float4(0, 0, 0, 0);
        amp  = logf(cnt1 + 1.f) * (1.0f / 2.19722457733621938f);   // / log(9)
        iamp = 1.f / amp;
    }

    if (fast) {
        __shared__ float S[16 * 64];   // [lane][feature]
        float* F = d_fsum + batch[n0] * 832;
#pragma unroll
        for (int c = 0; c < 13; c++) {
            float4 cv;
            if      (c == 0)  cv = xv;
            else if (c == 1)  cv = mean;
            else if (c == 2)  cv = vmn;
            else if (c == 3)  cv = vmx;
            else if (c == 4)  cv = sd;
            else if (c == 5)  cv = mul4(mean, amp);
            else if (c == 6)  cv = mul4(vmn, amp);
            else if (c == 7)  cv = mul4(vmx, amp);
            else if (c == 8)  cv = mul4(sd, amp);
            else if (c == 9)  cv = mul4(mean, iamp);
            else if (c == 10) cv = mul4(vmn, iamp);
            else if (c == 11) cv = mul4(vmx, iamp);
            else              cv = mul4(sd, iamp);
            *reinterpret_cast<float4*>(&S[lane * 64 + ft]) = cv;
            __syncthreads();
            if (tid < 64) {
                float s = 0.f;
#pragma unroll
                for (int l = 0; l < 16; l++) s += S[l * 64 + tid];
                atomicAdd(&F[c * 64 + tid], s);
            }
            __syncthreads();
        }
    } else if (valid) {
        float* F = d_fsum + batch[n] * 832;
        float4 ch[13];
        ch[0] = xv;  ch[1] = mean; ch[2] = vmn; ch[3] = vmx; ch[4] = sd;
        ch[5] = mul4(mean, amp);  ch[6]  = mul4(vmn, amp);  ch[7]  = mul4(vmx, amp);  ch[8]  = mul4(sd, amp);
        ch[9] = mul4(mean, iamp); ch[10] = mul4(vmn, iamp); ch[11] = mul4(vmx, iamp); ch[12] = mul4(sd, iamp);
#pragma unroll
        for (int c = 0; c < 13; c++) {
            atomicAdd(&F[c * 64 + ft + 0], ch[c].x);
            atomicAdd(&F[c * 64 + ft + 1], ch[c].y);
            atomicAdd(&F[c * 64 + ft + 2], ch[c].z);
            atomicAdd(&F[c * 64 + ft + 3], ch[c].w);
        }
    }
}

// ------------- z = (fsum/cnt) @ Wc + bc; self-cleans fsum ----------------------
__global__ __launch_bounds__(512) void zsmall_kernel(const int* __restrict__ batch, int Nn) {
    __shared__ float Fs[832];
    __shared__ float red[512];
    int g = blockIdx.x;
    int tid = threadIdx.x;
    int j = tid & 127, piece = tid >> 7;

    int lo = 0, hi = Nn;
    while (lo < hi) { int m = (lo + hi) >> 1; if (batch[m] < g) lo = m + 1; else hi = m; }
    int lo2 = lo, hi2 = Nn;
    while (lo2 < hi2) { int m = (lo2 + hi2) >> 1; if (batch[m] < g + 1) lo2 = m + 1; else hi2 = m; }
    float inv = 1.f / fmaxf((float)(lo2 - lo), 1.f);

    for (int i = tid; i < 832; i += 512) {
        Fs[i] = d_fsum[g * 832 + i] * inv;
        d_fsum[g * 832 + i] = 0.f;        // restore zero for next replay
    }
    __syncthreads();

    int k0 = piece * 208;
    float a0 = (piece == 0) ? d_bc[j] : 0.f, a1 = 0.f, a2 = 0.f, a3 = 0.f;
#pragma unroll 4
    for (int k = 0; k < 208; k += 4) {
        a0 = fmaf(Fs[k0 + k],     d_Wc[(k0 + k)     * 128 + j], a0);
        a1 = fmaf(Fs[k0 + k + 1], d_Wc[(k0 + k + 1) * 128 + j], a1);
        a2 = fmaf(Fs[k0 + k + 2], d_Wc[(k0 + k + 2) * 128 + j], a2);
        a3 = fmaf(Fs[k0 + k + 3], d_Wc[(k0 + k + 3) * 128 + j], a3);
    }
    red[tid] = (a0 + a1) + (a2 + a3);
    __syncthreads();
    if (piece == 0)
        d_z[g * 128 + j] = (red[j] + red[128 + j]) + (red[256 + j] + red[384 + j]);
}

// ------------------------------- MLP head --------------------------------------
__device__ __forceinline__ void mlp_stats(float ps, float pq2, int rr, int j,
                                          float* redS, float* redQ,
                                          float* sgS, float* sbS,
                                          const float* __restrict__ g,
                                          const float* __restrict__ be) {
    redS[rr * 128 + j] = ps;
    redQ[rr * 128 + j] = pq2;
    __syncthreads();
    if (rr == 0) {
        float s = 0.f, q = 0.f;
#pragma unroll
        for (int r = 0; r < 8; r++) { s += redS[r * 128 + j]; q += redQ[r * 128 + j]; }
        float mu  = s * (1.f / 64.f);
        float var = q * (1.f / 64.f) - mu * mu;
        float is  = rsqrtf(fmaxf(var, 0.f) + 1e-5f);
        float sg  = g[j] * is;
        sgS[j] = sg;
        sbS[j] = be[j] - mu * sg;
    }
    __syncthreads();
}

__device__ __forceinline__ void mlp_layer(float* S, float* redS, float* redQ,
                                          float* sgS, float* sbS,
                                          const float* __restrict__ W, const float* __restrict__ b,
                                          const float* __restrict__ g, const float* __restrict__ be,
                                          int rr, int j, float* rsave, const float* radd) {
    const int i0 = rr * 8;
    unsigned long long acc2[4];
    unsigned long long binit = dup2(b[j]);
#pragma unroll
    for (int p = 0; p < 4; p++) acc2[p] = binit;

    for (int k = 0; k < 128; k++) {
        unsigned long long w2 = dup2(W[k * 128 + j]);
        const unsigned long long* Z =
            reinterpret_cast<const unsigned long long*>(&S[k * 66 + i0]);
#pragma unroll
        for (int p = 0; p < 4; p++) acc2[p] = fma2(Z[p], w2, acc2[p]);
    }

    float acc[8];
#pragma unroll
    for (int p = 0; p < 4; p++) unpack2(acc2[p], acc[2 * p], acc[2 * p + 1]);

    float ps = 0.f, pq2 = 0.f;
#pragma unroll
    for (int u = 0; u < 8; u++) { ps += acc[u]; pq2 = fmaf(acc[u], acc[u], pq2); }
    mlp_stats(ps, pq2, rr, j, redS, redQ, sgS, sbS, g, be);   // syncs cover S reads

    float sg = sgS[j], sb = sbS[j];
#pragma unroll
    for (int p = 0; p < 4; p++) {
        float v0 = acc[2 * p] * sg + sb;
        float v1 = acc[2 * p + 1] * sg + sb;
        if (radd) { v0 += radd[2 * p]; v1 += radd[2 * p + 1]; }
        v0 = fmaxf(v0, 0.f);
        v1 = fmaxf(v1, 0.f);
        *reinterpret_cast<float2*>(&S[j * 66 + i0 + 2 * p]) = make_float2(v0, v1);
        if (rsave) { rsave[2 * p] = v0; rsave[2 * p + 1] = v1; }
    }
    __syncthreads();
}

__global__ __launch_bounds__(1024) void mlp_kernel(
        const float* __restrict__ g1,  const float* __restrict__ be1,
        const float* __restrict__ W2,  const float* __restrict__ b2,
        const float* __restrict__ g2,  const float* __restrict__ be2,
        const float* __restrict__ Wr1, const float* __restrict__ br1,
        const float* __restrict__ gr1, const float* __restrict__ ber1,
        const float* __restrict__ Wr2, const float* __restrict__ br2,
        const float* __restrict__ gr2, const float* __restrict__ ber2,
        const float* __restrict__ Wout, const float* __restrict__ bout,
        float* __restrict__ out) {
    __shared__ float S[128 * 66];        // transposed activations, padded
    __shared__ float redS[8 * 128];
    __shared__ float redQ[8 * 128];
    __shared__ float sgS[128], sbS[128];
    int tid = threadIdx.x;
    int rr = tid >> 7, j = tid & 127;
    const int i0 = rr * 8;

    float v8[8];
#pragma unroll
    for (int u = 0; u < 8; u++) v8[u] = d_z[(i0 + u) * 128 + j];
    {
        float ps = 0.f, pq2 = 0.f;
#pragma unroll
        for (int u = 0; u < 8; u++) { ps += v8[u]; pq2 = fmaf(v8[u], v8[u], pq2); }
        mlp_stats(ps, pq2, rr, j, redS, redQ, sgS, sbS, g1, be1);
        float sg = sgS[j], sb = sbS[j];
#pragma unroll
        for (int p = 0; p < 4; p++) {
            float v0 = fmaxf(v8[2 * p] * sg + sb, 0.f);
            float v1 = fmaxf(v8[2 * p + 1] * sg + sb, 0.f);
            *reinterpret_cast<float2*>(&S[j * 66 + i0 + 2 * p]) = make_float2(v0, v1);
        }
        __syncthreads();
    }

    float res[8];
    mlp_layer(S, redS, redQ, sgS, sbS, W2,  b2,  g2,  be2,  rr, j, res,    nullptr);
    mlp_layer(S, redS, redQ, sgS, sbS, Wr1, br1, gr1, ber1, rr, j, nullptr, nullptr);
    mlp_layer(S, redS, redQ, sgS, sbS, Wr2, br2, gr2, ber2, rr, j, nullptr, res);

    if (tid < 64) {
        float a = bout[0];
        for (int k = 0; k < 128; k++) a = fmaf(S[k * 66 + tid], Wout[k], a);
        out[tid] = a;
    }
}

// --------------------------------- launch --------------------------------------
extern "C" void kernel_launch(void* const* d_in, const int* in_sizes, int n_in,
                              void* d_out, int out_size) {
    const float* x      = (const float*)d_in[0];
    const int*   ei     = (const int*)d_in[1];
    const float* ea     = (const float*)d_in[2];
    const int*   batch  = (const int*)d_in[3];
    const float* W_edge = (const float*)d_in[4];
    const float* b_edge = (const float*)d_in[5];
    const float* W_pre  = (const float*)d_in[6];
    const float* b_pre  = (const float*)d_in[7];
    const float* W_post = (const float*)d_in[8];
    const float* b_post = (const float*)d_in[9];
    const float* W_lin  = (const float*)d_in[10];
    const float* b_lin  = (const float*)d_in[11];
    const float* g1  = (const float*)d_in[12];
    const float* be1 = (const float*)d_in[13];
    const float* W2  = (const float*)d_in[14];
    const float* b2  = (const float*)d_in[15];
    const float* g2  = (const float*)d_in[16];
    const float* be2 = (const float*)d_in[17];
    const float* Wr1 = (const float*)d_in[18];
    const float* br1 = (const float*)d_in[19];
    const float* gr1 = (const float*)d_in[20];
    const float* ber1= (const float*)d_in[21];
    const float* Wr2 = (const float*)d_in[22];
    const float* br2 = (const float*)d_in[23];
    const float* gr2 = (const float*)d_in[24];
    const float* ber2= (const float*)d_in[25];
    const float* Wout= (const float*)d_in[26];
    const float* bout= (const float*)d_in[27];
    float* out = (float*)d_out;

    const int Nn = in_sizes[0] / 64;
    const int E  = in_sizes[2];
    const int NB = (Nn + 255) / 256;

    void *p_pq, *p_Wds, *p_Wc;
    cudaGetSymbolAddress(&p_pq,  d_pq);
    cudaGetSymbolAddress(&p_Wds, d_Wds);
    cudaGetSymbolAddress(&p_Wc,  d_Wc);

    // one-time stream/event resources (resource caching only; captured work is
    // identical on every call — record/wait are re-issued each launch)
    static cudaStream_t s_csr = nullptr;
    static cudaEvent_t  ev_fork = nullptr, ev_join = nullptr, ev_wc = nullptr;
    if (!s_csr) {
        cudaStreamCreateWithFlags(&s_csr, cudaStreamNonBlocking);
        cudaEventCreateWithFlags(&ev_fork, cudaEventDisableTiming);
        cudaEventCreateWithFlags(&ev_join, cudaEventDisableTiming);
        cudaEventCreateWithFlags(&ev_wc,   cudaEventDisableTiming);
    }

    // fork: CSR chain (+Wc) on s_csr, prep/pq on the launch stream
    cudaEventRecord(ev_fork, 0);
    cudaStreamWaitEvent(s_csr, ev_fork, 0);

    initdeg_kernel<<<NB, 256, 0, s_csr>>>(Nn);
    count_kernel<<<(E + 255) / 256, 256, 0, s_csr>>>(ei, E);
    scan_kernel<<<SCAN_G, SCAN_T, 0, s_csr>>>(Nn);
    scatter_kernel<<<(E + 255) / 256, 256, 0, s_csr>>>(ei, ea, E);
    cudaEventRecord(ev_join, s_csr);
    // Wc = W_post @ W_lin (only needed by zsmall) — overlaps agg on main stream
    {
        dim3 g((832 + 127) / 128, 1);
        sgemm_kernel<<<g, 256, 0, s_csr>>>(W_post, W_lin, nullptr, (float*)p_Wc,
                                           832, 128, 128, 128, 128);
    }
    cudaEventRecord(ev_wc, s_csr);

    prep_kernel<<<(64 * 128 + 128 + 64 + 255) / 256, 256>>>(W_edge, b_edge, W_pre, b_pre,
                                                            b_post, W_lin, b_lin);
    // pq = x @ [Wd|Ws]      [N,64] @ [64,128]
    {
        dim3 g((Nn + 127) / 128, 1);
        sgemm_kernel<<<g, 256>>>(x, (const float*)p_Wds, nullptr, (float*)p_pq,
                                 Nn, 64, 64, 128, 128);
    }

    // join: aggregation needs CSR + pq + v/cvec(prep)
    cudaStreamWaitEvent(0, ev_join, 0);
    agg_kernel<<<(Nn + 15) / 16, 256>>>(batch, x, Nn);
    cudaStreamWaitEvent(0, ev_wc, 0);
    zsmall_kernel<<<GNUM, 512>>>(batch, Nn);
    mlp_kernel<<<1, 1024>>>(g1, be1, W2, b2, g2, be2, Wr1, br1, gr1, ber1,
                            Wr2, br2, gr2, ber2, Wout, bout, out);
}